// round 11
// baseline (speedup 1.0000x reference)
#include <cuda_runtime.h>
#include <cuda_bf16.h>
#include <math.h>
#include <stdint.h>

// Problem constants
#define NB   8
#define TT   512
#define DD   1024
#define TA   256
#define TB2  256
#define RM   128
#define TMM  384
#define NH   16
#define HD   64
#define NBINS 16384
#define CAP   4096
#define TARGETN 2048
#define SS   (TMM*TMM)
#define W3   (3*DD)

// ---------------- static device scratch ----------------
__device__ float              g_inorm[NB*TT];
__device__ unsigned int       g_keys[NB*65536];
__device__ unsigned int       g_hist[NB*NBINS];
__device__ int                g_thr[NB];
__device__ int                g_cnt[NB];
__device__ unsigned long long g_gath[NB*CAP];
__device__ int                g_amap[NB*TA];
__device__ int                g_bmap[NB*TB2];
__device__ int                g_kept[NB*RM];
// pre-split bf16 (hi/lo) operand buffers
__device__ unsigned short g_xh [NB*TT*DD],    g_xl [NB*TT*DD];     // all 512 tokens
__device__ unsigned short g_wch[3*DD*DD],     g_wcl[3*DD*DD];      // Wq|Wk|Wv stacked
__device__ unsigned short g_woh[DD*DD],       g_wol[DD*DD];        // Wo
__device__ unsigned short g_qkh[NB*TT*3*DD],  g_qkl[NB*TT*3*DD];   // QKV of all 512 tokens
__device__ unsigned short g_mqh[NB*TMM*3*DD], g_mql[NB*TMM*3*DD];  // merged QKV (384 rows)
__device__ float          g_s  [NB*NH*SS];                          // scores (fp32)
__device__ unsigned short g_ph [NB*NH*SS],    g_pl [NB*NH*SS];     // softmax probs
__device__ unsigned short g_aoh[NB*TMM*DD],   g_aol[NB*TMM*DD];    // attn out
__device__ float          g_pr [NB*TMM*DD];                         // final proj

// ---------------- helpers ----------------
__device__ __forceinline__ unsigned pk2u(unsigned short a, unsigned short b) {
    return (unsigned)a | ((unsigned)b << 16);
}
__device__ __forceinline__ void split2u(float v, unsigned short& h, unsigned short& l) {
    __nv_bfloat16 hb = __float2bfloat16_rn(v);
    __nv_bfloat16 lb = __float2bfloat16_rn(v - __bfloat162float(hb));
    h = __bfloat16_as_ushort(hb);
    l = __bfloat16_as_ushort(lb);
}
__device__ __forceinline__ float join2u(unsigned short h, unsigned short l) {
    return __bfloat162float(__ushort_as_bfloat16(h)) + __bfloat162float(__ushort_as_bfloat16(l));
}

// ---------------- init ----------------
__global__ void k_init() {
    int i = blockIdx.x * blockDim.x + threadIdx.x;
    if (i < NB*NBINS) g_hist[i] = 0u;
    if (i < NB)       g_cnt[i]  = 0;
}

// ---------------- row inverse norms ----------------
__global__ void k_norm(const float* __restrict__ x) {
    int row  = blockIdx.x * 8 + (threadIdx.x >> 5);
    if (row >= NB*TT) return;
    int lane = threadIdx.x & 31;
    const float* p = x + (size_t)row * DD;
    float ss = 0.f;
    for (int i = lane; i < DD; i += 32) { float v = p[i]; ss += v*v; }
    #pragma unroll
    for (int o = 16; o; o >>= 1) ss += __shfl_xor_sync(0xffffffffu, ss, o);
    if (lane == 0) g_inorm[row] = 1.0f / fmaxf(sqrtf(ss), 1e-12f);
}

// ---------------- weight convert/split ----------------
__global__ void k_cvtW(const float* __restrict__ Wq, const float* __restrict__ Wk,
                       const float* __restrict__ Wv, const float* __restrict__ Wo) {
    int t = blockIdx.x * blockDim.x + threadIdx.x;
    int which = t >> 18, rem = t & 262143;
    const float* src = (which == 0) ? Wq : (which == 1) ? Wk : (which == 2) ? Wv : Wo;
    float4 v = *(const float4*)(src + (size_t)rem * 4);
    unsigned short h0,h1,h2,h3,l0,l1,l2,l3;
    split2u(v.x,h0,l0); split2u(v.y,h1,l1); split2u(v.z,h2,l2); split2u(v.w,h3,l3);
    uint2 hh = make_uint2(pk2u(h0,h1), pk2u(h2,h3));
    uint2 ll = make_uint2(pk2u(l0,l1), pk2u(l2,l3));
    if (which < 3) {
        *(uint2*)(g_wch + (size_t)t*4) = hh;
        *(uint2*)(g_wcl + (size_t)t*4) = ll;
    } else {
        *(uint2*)(g_woh + (size_t)rem*4) = hh;
        *(uint2*)(g_wol + (size_t)rem*4) = ll;
    }
}

// ---------------- x convert/split: all 512 tokens ----------------
__global__ void k_cvtX(const float* __restrict__ x) {
    int t = blockIdx.x * blockDim.x + threadIdx.x;     // 1,048,576 float4 slots
    float4 v = *(const float4*)(x + (size_t)t * 4);
    unsigned short h0,h1,h2,h3,l0,l1,l2,l3;
    split2u(v.x,h0,l0); split2u(v.y,h1,l1); split2u(v.z,h2,l2); split2u(v.w,h3,l3);
    *(uint2*)(g_xh + (size_t)t*4) = make_uint2(pk2u(h0,h1), pk2u(h2,h3));
    *(uint2*)(g_xl + (size_t)t*4) = make_uint2(pk2u(l0,l1), pk2u(l2,l3));
}

// ---------------- cosine sims (fp32, 64x32 tile) ----------------
__global__ void k_sim(const float* __restrict__ x) {
    int b  = blockIdx.z;
    int a0 = blockIdx.y * 64;
    int b0 = blockIdx.x * 32;
    int tid = threadIdx.x;
    int tx = tid & 15, ty = tid >> 4;
    __shared__ float As[16][68], Bs[16][36];
    const float* xb = x + (size_t)b * TT * DD;
    float acc[4][2];
    #pragma unroll
    for (int i = 0; i < 4; i++) { acc[i][0] = 0.f; acc[i][1] = 0.f; }

    int ar = tid >> 2, aq = tid & 3;
    for (int k0 = 0; k0 < DD; k0 += 16) {
        float4 va = *(const float4*)(xb + (size_t)(2*(a0+ar)) * DD + k0 + aq*4);
        As[aq*4+0][ar]=va.x; As[aq*4+1][ar]=va.y; As[aq*4+2][ar]=va.z; As[aq*4+3][ar]=va.w;
        if (tid < 128) {
            int br = tid >> 2, bq = tid & 3;
            float4 vb = *(const float4*)(xb + (size_t)(2*(b0+br)+1) * DD + k0 + bq*4);
            Bs[bq*4+0][br]=vb.x; Bs[bq*4+1][br]=vb.y; Bs[bq*4+2][br]=vb.z; Bs[bq*4+3][br]=vb.w;
        }
        __syncthreads();
        #pragma unroll
        for (int kk = 0; kk < 16; kk++) {
            float4 a4 = *(const float4*)&As[kk][ty*4];
            float2 b2 = *(const float2*)&Bs[kk][tx*2];
            acc[0][0] += a4.x*b2.x; acc[0][1] += a4.x*b2.y;
            acc[1][0] += a4.y*b2.x; acc[1][1] += a4.y*b2.y;
            acc[2][0] += a4.z*b2.x; acc[2][1] += a4.z*b2.y;
            acc[3][0] += a4.w*b2.x; acc[3][1] += a4.w*b2.y;
        }
        __syncthreads();
    }
    float ina[4], inb[2];
    #pragma unroll
    for (int i = 0; i < 4; i++) ina[i] = g_inorm[b*TT + 2*(a0+ty*4+i)];
    #pragma unroll
    for (int j = 0; j < 2; j++) inb[j] = g_inorm[b*TT + 2*(b0+tx*2+j) + 1];
    #pragma unroll
    for (int i = 0; i < 4; i++)
        #pragma unroll
        for (int j = 0; j < 2; j++) {
            float sim = acc[i][j] * ina[i] * inb[j];
            unsigned u = __float_as_uint(sim);
            u = (u & 0x80000000u) ? ~u : (u | 0x80000000u);
            int idx = (a0+ty*4+i) * TB2 + (b0+tx*2+j);
            g_keys[b*65536 + idx] = u;
            atomicAdd(&g_hist[b*NBINS + (u >> 18)], 1u);
        }
}

// ---------------- per-batch threshold bin ----------------
__global__ void k_thresh() {
    int b = blockIdx.x, t = threadIdx.x;
    __shared__ unsigned int csum[256];
    unsigned int s = 0;
    for (int j = 0; j < 64; j++) s += g_hist[b*NBINS + (NBINS-1 - (t*64 + j))];
    csum[t] = s;
    __syncthreads();
    if (t == 0) {
        unsigned int acc = 0; int thr = 0;
        int c = 0;
        for (; c < 256; c++) { if (acc + csum[c] >= TARGETN) break; acc += csum[c]; }
        if (c < 256) {
            int binBase = NBINS - 1 - c*64;
            for (int j = 0; j < 64; j++) {
                int bin = binBase - j;
                acc += g_hist[b*NBINS + bin];
                if (acc >= TARGETN) { thr = bin; break; }
            }
        }
        g_thr[b] = thr;
    }
}

// ---------------- gather top entries ----------------
__global__ void k_gather() {
    int i = blockIdx.x * blockDim.x + threadIdx.x;
    int b = i >> 16, idx = i & 65535;
    unsigned int key = g_keys[i];
    if ((int)(key >> 18) >= g_thr[b]) {
        int pos = atomicAdd(&g_cnt[b], 1);
        if (pos < CAP)
            g_gath[b*CAP + pos] =
                ((unsigned long long)key << 16) | (unsigned long long)(65535 - idx);
    }
}

// ---------------- bitonic sort + serial greedy + maps ----------------
__global__ void k_sortgreedy() {
    int b = blockIdx.x, tid = threadIdx.x;
    __shared__ unsigned long long S[CAP];
    __shared__ unsigned long long red[1024];
    __shared__ unsigned char ua[TA], ub[TB2];
    __shared__ int pa[RM], pb[RM];
    __shared__ int sm_cnt;

    int cnt = g_cnt[b];
    int lim = (cnt <= CAP) ? cnt : 0;
    for (int i = tid; i < CAP; i += 1024) S[i] = (i < lim) ? g_gath[b*CAP + i] : 0ULL;
    for (int i = tid; i < TA;  i += 1024) { ua[i] = 0; ub[i] = 0; }
    if (tid == 0) sm_cnt = 0;
    __syncthreads();

    for (int size = 2; size <= CAP; size <<= 1)
        for (int stride = size >> 1; stride > 0; stride >>= 1) {
            for (int t = tid; t < CAP/2; t += 1024) {
                int pos = 2*t - (t & (stride - 1));
                unsigned long long x0 = S[pos], x1 = S[pos + stride];
                bool up = ((pos & size) == 0);
                if (up ? (x0 < x1) : (x0 > x1)) { S[pos] = x1; S[pos + stride] = x0; }
            }
            __syncthreads();
        }

    if (tid == 0) {
        int m = 0;
        for (int i = 0; i < CAP && m < RM; i++) {
            unsigned long long e = S[i];
            if (!e) break;
            int idx = 65535 - (int)(e & 0xFFFFULL);
            int a = idx >> 8, bb = idx & 255;
            if (!ua[a] && !ub[bb]) { ua[a] = 1; ub[bb] = 1; pa[m] = a; pb[m] = bb; m++; }
        }
        sm_cnt = m;
    }
    __syncthreads();

    while (sm_cnt < RM) {
        unsigned long long best = 0ULL;
        for (int i = tid; i < 65536; i += 1024) {
            int a = i >> 8, bb = i & 255;
            if (ua[a] || ub[bb]) continue;
            unsigned long long comp =
                ((unsigned long long)g_keys[b*65536 + i] << 16) |
                (unsigned long long)(65535 - i);
            if (comp > best) best = comp;
        }
        red[tid] = best;
        __syncthreads();
        for (int o = 512; o; o >>= 1) {
            if (tid < o) { unsigned long long v = red[tid + o]; if (v > red[tid]) red[tid] = v; }
            __syncthreads();
        }
        if (tid == 0) {
            unsigned long long e = red[0];
            int idx = 65535 - (int)(e & 0xFFFFULL);
            int a = idx >> 8, bb = idx & 255;
            ua[a] = 1; ub[bb] = 1; pa[sm_cnt] = a; pb[sm_cnt] = bb; sm_cnt++;
        }
        __syncthreads();
    }

    if (tid == 0) {
        for (int a = 0; a < TA; a++) g_amap[b*TA + a] = -1;
        for (int i = 0; i < RM; i++) g_amap[b*TA + pa[i]] = pb[i];
        int k = 0;
        for (int bb = 0; bb < TB2; bb++)
            if (!ub[bb]) { g_kept[b*RM + k] = bb; g_bmap[b*TB2 + bb] = TA + k; k++; }
        for (int i = 0; i < RM; i++) g_bmap[b*TB2 + pb[i]] = pa[i];
    }
}

// ---------------- merge in PROJECTION space: build merged Q|K|V (384 rows) ----------------
__global__ void k_mergeQKV() {
    int b = blockIdx.y, r = blockIdx.x, tid = threadIdx.x;   // 256 threads
    size_t dst = ((size_t)b*TMM + r) * W3;
    int mb = (r < TA) ? g_amap[b*TA + r] : -1;
    int src0 = (r < TA) ? 2*r : 2*g_kept[b*RM + (r - TA)] + 1;
    size_t s0 = ((size_t)b*TT + src0) * W3;
    if (r < TA && mb >= 0) {
        size_t s1 = ((size_t)b*TT + 2*mb + 1) * W3;
        for (int i = tid; i < W3/4; i += 256) {
            uint2 h0 = *(const uint2*)(g_qkh + s0 + i*4);
            uint2 l0 = *(const uint2*)(g_qkl + s0 + i*4);
            uint2 h1 = *(const uint2*)(g_qkh + s1 + i*4);
            uint2 l1 = *(const uint2*)(g_qkl + s1 + i*4);
            unsigned short oh[4], ol[4];
            #pragma unroll
            for (int j = 0; j < 4; j++) {
                unsigned hw0 = (j < 2) ? h0.x : h0.y, lw0 = (j < 2) ? l0.x : l0.y;
                unsigned hw1 = (j < 2) ? h1.x : h1.y, lw1 = (j < 2) ? l1.x : l1.y;
                int sh = (j & 1) * 16;
                float va = join2u((unsigned short)(hw0 >> sh), (unsigned short)(lw0 >> sh));
                float vb = join2u((unsigned short)(hw1 >> sh), (unsigned short)(lw1 >> sh));
                split2u(0.5f*(va + vb), oh[j], ol[j]);
            }
            *(uint2*)(g_mqh + dst + i*4) = make_uint2(pk2u(oh[0],oh[1]), pk2u(oh[2],oh[3]));
            *(uint2*)(g_mql + dst + i*4) = make_uint2(pk2u(ol[0],ol[1]), pk2u(ol[2],ol[3]));
        }
    } else {
        for (int i = tid; i < W3/4; i += 256) {
            *(uint2*)(g_mqh + dst + i*4) = *(const uint2*)(g_qkh + s0 + i*4);
            *(uint2*)(g_mql + dst + i*4) = *(const uint2*)(g_qkl + s0 + i*4);
        }
    }
}

// =======================================================================
//  Pre-split bf16x3 tensor-core GEMM, cp.async double-buffered, ldmatrix.
// =======================================================================
#define BK 32
#define SROW 40
#define ARR_ELEMS (128*SROW)
#define STAGE_ELEMS (4*ARR_ELEMS)
#define SMEM_BYTES (2*STAGE_ELEMS*2)

#define MMA_BF16(d, a, b) \
    asm volatile("mma.sync.aligned.m16n8k16.row.col.f32.bf16.bf16.f32 " \
                 "{%0,%1,%2,%3},{%4,%5,%6,%7},{%8,%9},{%0,%1,%2,%3};" \
                 : "+f"(d[0]), "+f"(d[1]), "+f"(d[2]), "+f"(d[3]) \
                 : "r"(a[0]), "r"(a[1]), "r"(a[2]), "r"(a[3]), "r"(b[0]), "r"(b[1]))

__device__ __forceinline__ void cp16(unsigned short* dst, const unsigned short* src) {
    unsigned s = (unsigned)__cvta_generic_to_shared(dst);
    asm volatile("cp.async.cg.shared.global [%0], [%1], 16;\n" :: "r"(s), "l"(src));
}

__device__ __forceinline__ void ldsmA(unsigned r[4], const unsigned short* base,
                                      int row0, int col0, int lane) {
    const unsigned short* p = base + (size_t)(row0 + ((lane>>3)&1)*8 + (lane&7))*SROW
                                   + col0 + ((lane>>4)&1)*8;
    unsigned a = (unsigned)__cvta_generic_to_shared(p);
    asm volatile("ldmatrix.sync.aligned.m8n8.x4.shared.b16 {%0,%1,%2,%3},[%4];"
                 : "=r"(r[0]), "=r"(r[1]), "=r"(r[2]), "=r"(r[3]) : "r"(a));
}
__device__ __forceinline__ void ldsmB(unsigned r[4], const unsigned short* base,
                                      int row0, int col0, int lane) {
    const unsigned short* p = base + (size_t)(row0 + ((lane>>4)&1)*8 + (lane&7))*SROW
                                   + col0 + ((lane>>3)&1)*8;
    unsigned a = (unsigned)__cvta_generic_to_shared(p);
    asm volatile("ldmatrix.sync.aligned.m8n8.x4.shared.b16 {%0,%1,%2,%3},[%4];"
                 : "=r"(r[0]), "=r"(r[1]), "=r"(r[2]), "=r"(r[3]) : "r"(a));
}

__global__ __launch_bounds__(512)
void k_mma2(const unsigned short* __restrict__ Ahg, const unsigned short* __restrict__ Alg,
            const unsigned short* __restrict__ Bhg, const unsigned short* __restrict__ Blg,
            float* __restrict__ Cf, unsigned short* __restrict__ Ch, unsigned short* __restrict__ Cl,
            int M, int N, int K,
            long sAm, long sBn, long sBk, long sCm,
            long bAo, long bAi, long bBo, long bBi, long bCo, long bCi,
            int inner, float alpha, int modeB, int nlay)
{
    extern __shared__ unsigned short sm_[];
    int z = blockIdx.z, zo = z / inner, zi = z % inner;
    Ahg += (size_t)zo*bAo + (size_t)zi*bAi;
    Alg += (size_t)zo*bAo + (size_t)zi*bAi;
    Bhg += (size_t)zo*bBo + (size_t)zi*bBi;
    Blg += (size_t)zo*bBo + (size_t)zi*bBi;
    size_t coff = (size_t)zo*bCo + (size_t)zi*bCi;
    int m0 = blockIdx.y * 128, n0 = blockIdx.x * 128;

    int tid  = threadIdx.x;
    int warp = tid >> 5, lane = tid & 31;
    int g    = lane >> 2, tg = lane & 3;
    int wm, wn, MT;
    if (!nlay) { wm = (warp >> 2) * 32; wn = (warp & 3) * 32; MT = 2; }
    else       { wm = (warp & 7) * 16;  wn = (warp >> 3) * 32; MT = 1; }

    float acc[2][4][4];
    #pragma unroll
    for (int i = 0; i < 2; i++)
        #pragma unroll
        for (int j = 0; j < 4; j++)
            #pragma unroll
            for (int c = 0; c < 4; c++) acc[i][j][c] = 0.f;

    const int ntiles = K / BK;

    auto fill = [&](int stage, int k0) {
        unsigned short* sb = sm_ + stage * STAGE_ELEMS;
        if (!modeB) {
            #pragma unroll
            for (int i = 0; i < 4; i++) {
                int c = tid + i*512;
                int arr = c >> 9, rem = c & 511;
                int row = rem >> 2, q = rem & 3;
                const unsigned short* src;
                if      (arr == 0) src = Ahg + (size_t)(m0+row)*sAm + k0 + q*8;
                else if (arr == 1) src = Alg + (size_t)(m0+row)*sAm + k0 + q*8;
                else if (arr == 2) src = Bhg + (size_t)(n0+row)*sBn + k0 + q*8;
                else               src = Blg + (size_t)(n0+row)*sBn + k0 + q*8;
                cp16(sb + arr*ARR_ELEMS + row*SROW + q*8, src);
            }
        } else {
            #pragma unroll
            for (int i = 0; i < 2; i++) {
                int c = tid + i*512;
                int arr = c >> 9, rem = c & 511;
                int row = rem >> 2, q = rem & 3;
                const unsigned short* src = (arr ? Alg : Ahg) + (size_t)(m0+row)*sAm + k0 + q*8;
                cp16(sb + arr*ARR_ELEMS + row*SROW + q*8, src);
            }
            #pragma unroll
            for (int i = 0; i < 8; i++) {
                int s = tid + i*512;
                int n = s & 127, kk = s >> 7;
                int gn = n0 + n;
                if (gn < N) {
                    size_t off = (size_t)gn + (size_t)(k0 + kk) * sBk;
                    sb[2*ARR_ELEMS + n*SROW + kk] = Bhg[off];
                    sb[3*ARR_ELEMS + n*SROW + kk] = Blg[off];
                }
            }
        }
    };

    fill(0, 0);
    asm volatile("cp.async.commit_group;\n");

    for (int t = 0; t < ntiles; t++) {
        if (t + 1 < ntiles) fill((t+1) & 1, (t+1)*BK);
        asm volatile("cp.async.commit_group;\n");
        asm volatile("cp.async.wait_group 1;\n");
        __syncthreads();

        const unsigned short* sb = sm_ + (t & 1) * STAGE_ELEMS;
        const unsigned short* Ahs = sb;
        const unsigned short* Als = sb + ARR_ELEMS;
        const unsigned short* Bhs = sb + 2*ARR_ELEMS;
        const unsigned short* Bls = sb + 3*ARR_ELEMS;

        #pragma unroll
        for (int kc = 0; kc < 2; kc++) {
            int kb = kc*16;
            unsigned ah[2][4], al[2][4], bh[4][2], bl[4][2];
            #pragma unroll
            for (int mt = 0; mt < 2; mt++) {
                if (mt < MT) {
                    ldsmA(ah[mt], Ahs, wm + mt*16, kb, lane);
                    ldsmA(al[mt], Als, wm + mt*16, kb, lane);
                }
            }
            {
                unsigned tmp[4];
                ldsmB(tmp, Bhs, wn, kb, lane);
                bh[0][0]=tmp[0]; bh[0][1]=tmp[1]; bh[1][0]=tmp[2]; bh[1][1]=tmp[3];
                ldsmB(tmp, Bhs, wn + 16, kb, lane);
                bh[2][0]=tmp[0]; bh[2][1]=tmp[1]; bh[3][0]=tmp[2]; bh[3][1]=tmp[3];
                ldsmB(tmp, Bls, wn, kb, lane);
                bl[0][0]=tmp[0]; bl[0][1]=tmp[1]; bl[1][0]=tmp[2]; bl[1][1]=tmp[3];
                ldsmB(tmp, Bls, wn + 16, kb, lane);
                bl[2][0]=tmp[0]; bl[2][1]=tmp[1]; bl[3][0]=tmp[2]; bl[3][1]=tmp[3];
            }
            #pragma unroll
            for (int mt = 0; mt < 2; mt++) if (mt < MT)
                #pragma unroll
                for (int nt = 0; nt < 4; nt++) MMA_BF16(acc[mt][nt], ah[mt], bh[nt]);
            #pragma unroll
            for (int mt = 0; mt < 2; mt++) if (mt < MT)
                #pragma unroll
                for (int nt = 0; nt < 4; nt++) MMA_BF16(acc[mt][nt], ah[mt], bl[nt]);
            #pragma unroll
            for (int mt = 0; mt < 2; mt++) if (mt < MT)
                #pragma unroll
                for (int nt = 0; nt < 4; nt++) MMA_BF16(acc[mt][nt], al[mt], bh[nt]);
        }
        __syncthreads();
    }

    // ---- epilogue ----
    #pragma unroll
    for (int mt = 0; mt < 2; mt++) {
        if (mt >= MT) continue;
        #pragma unroll
        for (int nt = 0; nt < 4; nt++) {
            int gm = m0 + wm + mt*16 + g;
            int gn = n0 + wn + nt*8 + 2*tg;
            if (gn >= N) continue;
            float v0 = alpha*acc[mt][nt][0], v1 = alpha*acc[mt][nt][1];
            float v2 = alpha*acc[mt][nt][2], v3 = alpha*acc[mt][nt][3];
            if (Cf) {
                if (gm < M)     *(float2*)(Cf + coff + (size_t)gm*sCm + gn)     = make_float2(v0, v1);
                if (gm + 8 < M) *(float2*)(Cf + coff + (size_t)(gm+8)*sCm + gn) = make_float2(v2, v3);
            }
            if (Ch) {
                unsigned short h0,h1,h2,h3,l0,l1,l2,l3;
                split2u(v0,h0,l0); split2u(v1,h1,l1); split2u(v2,h2,l2); split2u(v3,h3,l3);
                if (gm < M) {
                    *(unsigned*)(Ch + coff + (size_t)gm*sCm + gn) = pk2u(h0,h1);
                    *(unsigned*)(Cl + coff + (size_t)gm*sCm + gn) = pk2u(l0,l1);
                }
                if (gm + 8 < M) {
                    *(unsigned*)(Ch + coff + (size_t)(gm+8)*sCm + gn) = pk2u(h2,h3);
                    *(unsigned*)(Cl + coff + (size_t)(gm+8)*sCm + gn) = pk2u(l2,l3);
                }
            }
        }
    }
}

// ---------------- softmax over rows of 384 ----------------
__global__ void k_softmax() {
    int row = blockIdx.x, tid = threadIdx.x;
    float* p = g_s + (size_t)row * TMM;
    float v0 = p[tid], v1 = p[tid + 128], v2 = p[tid + 256];
    float mx = fmaxf(v0, fmaxf(v1, v2));
    __shared__ float sw[4], sw2[4];
    #pragma unroll
    for (int o = 16; o; o >>= 1) mx = fmaxf(mx, __shfl_xor_sync(0xffffffffu, mx, o));
    if ((tid & 31) == 0) sw[tid >> 5] = mx;
    __syncthreads();
    mx = fmaxf(fmaxf(sw[0], sw[1]), fmaxf(sw[2], sw[3]));
    v0 = expf(v0 - mx); v1 = expf(v1 - mx); v2 = expf(v2 - mx);
    float s = v0 + v1 + v2;
    #pragma unroll
    for (int o = 16; o; o >>= 1) s += __shfl_xor_sync(0xffffffffu, s, o);
    if ((tid & 31) == 0) sw2[tid >> 5] = s;
    __syncthreads();
    s = sw2[0] + sw2[1] + sw2[2] + sw2[3];
    float inv = 1.0f / s;
    size_t base = (size_t)row * TMM;
    unsigned short h, l;
    split2u(v0*inv, h, l); g_ph[base + tid]       = h; g_pl[base + tid]       = l;
    split2u(v1*inv, h, l); g_ph[base + tid + 128] = h; g_pl[base + tid + 128] = l;
    split2u(v2*inv, h, l); g_ph[base + tid + 256] = h; g_pl[base + tid + 256] = l;
}

// ---------------- unmerge into output ----------------
__global__ void k_unmerge(float* __restrict__ out) {
    int b = blockIdx.y, t = blockIdx.x, tid = threadIdx.x;
    int src = (t & 1) ? g_bmap[b*TB2 + (t >> 1)] : (t >> 1);
    const float4* s = (const float4*)(g_pr + ((size_t)b*TMM + src) * DD);
    float4* d = (float4*)(out + ((size_t)b*TT + t) * DD);
    d[tid] = s[tid];
}

// ---------------- launch ----------------
extern "C" void kernel_launch(void* const* d_in, const int* in_sizes, int n_in,
                              void* d_out, int out_size) {
    (void)in_sizes; (void)n_in; (void)out_size;
    const float* x  = (const float*)d_in[0];
    const float* Wq = (const float*)d_in[1];
    const float* Wk = (const float*)d_in[2];
    const float* Wv = (const float*)d_in[3];
    const float* Wo = (const float*)d_in[4];
    float* out = (float*)d_out;

    static cudaStream_t s1 = nullptr;
    static cudaEvent_t evRoot = nullptr, evMatch = nullptr;
    if (!s1) {
        cudaFuncSetAttribute(k_mma2, cudaFuncAttributeMaxDynamicSharedMemorySize, SMEM_BYTES);
        cudaStreamCreateWithFlags(&s1, cudaStreamNonBlocking);
        cudaEventCreateWithFlags(&evRoot,  cudaEventDisableTiming);
        cudaEventCreateWithFlags(&evMatch, cudaEventDisableTiming);
    }

    unsigned short *pxh,*pxl,*pwch,*pwcl,*pwoh,*pwol,*pqkh,*pqkl,*pmqh,*pmql,*pph,*ppl,*paoh,*paol;
    float *ps, *ppr;
    cudaGetSymbolAddress((void**)&pxh,  g_xh);  cudaGetSymbolAddress((void**)&pxl,  g_xl);
    cudaGetSymbolAddress((void**)&pwch, g_wch); cudaGetSymbolAddress((void**)&pwcl, g_wcl);
    cudaGetSymbolAddress((void**)&pwoh, g_woh); cudaGetSymbolAddress((void**)&pwol, g_wol);
    cudaGetSymbolAddress((void**)&pqkh, g_qkh); cudaGetSymbolAddress((void**)&pqkl, g_qkl);
    cudaGetSymbolAddress((void**)&pmqh, g_mqh); cudaGetSymbolAddress((void**)&pmql, g_mql);
    cudaGetSymbolAddress((void**)&pph,  g_ph);  cudaGetSymbolAddress((void**)&ppl,  g_pl);
    cudaGetSymbolAddress((void**)&paoh, g_aoh); cudaGetSymbolAddress((void**)&paol, g_aol);
    cudaGetSymbolAddress((void**)&ps,   g_s);   cudaGetSymbolAddress((void**)&ppr,  g_pr);

    // ---- fork: match pipeline on s1 (independent of projections) ----
    cudaEventRecord(evRoot, 0);
    cudaStreamWaitEvent(s1, evRoot, 0);
    k_init<<<(NB*NBINS + 255)/256, 256, 0, s1>>>();
    k_norm<<<NB*TT/8, 256, 0, s1>>>(x);
    k_sim<<<dim3(8, 4, NB), 256, 0, s1>>>(x);
    k_thresh<<<NB, 256, 0, s1>>>();
    k_gather<<<512, 1024, 0, s1>>>();
    k_sortgreedy<<<NB, 1024, 0, s1>>>();
    cudaEventRecord(evMatch, s1);

    // ---- main stream: convert + project ALL 512 tokens (no match dependency) ----
    k_cvtW<<<4096, 256>>>(Wq, Wk, Wv, Wo);
    k_cvtX<<<4096, 256>>>(x);
    // QKV projection of all tokens: (4096 x 3072) = x(4096x1024) @ Wcat^T -> split bf16
    k_mma2<<<dim3(24, 32, 1), 512, SMEM_BYTES>>>(
        pxh, pxl, pwch, pwcl, nullptr, pqkh, pqkl,
        NB*TT, 3*DD, DD,
        DD, DD, 0, 3*DD,
        0,0, 0,0, 0,0, 1, 1.0f, 0, 0);

    // ---- join: merge in projection space ----
    cudaStreamWaitEvent(0, evMatch, 0);
    k_mergeQKV<<<dim3(TMM, NB), 256>>>();

    const long MD3 = (long)TMM * W3;

    // scores: per (b,h): (384x384) = Q_bh @ K_bh^T / 8  -> fp32
    k_mma2<<<dim3(3, 3, NB*NH), 512, SMEM_BYTES>>>(
        pmqh, pmql, pmqh + DD, pmql + DD, ps, nullptr, nullptr,
        TMM, TMM, HD,
        W3, W3, 0, TMM,
        MD3, (long)HD, MD3, (long)HD, (long)NH*SS, (long)SS, NH, 0.125f, 0, 0);

    k_softmax<<<NB*NH*TMM, 128>>>();

    // attn @ V: per (b,h): (384x64) = P @ V_bh
    k_mma2<<<dim3(1, 3, NB*NH), 512, SMEM_BYTES>>>(
        pph, ppl, pmqh + 2*DD, pmql + 2*DD, nullptr, paoh, paol,
        TMM, HD, TMM,
        TMM, 0, W3, DD,
        (long)NH*SS, (long)SS, MD3, (long)HD, (long)TMM*DD, (long)HD, NH, 1.0f, 1, 1);

    // output projection -> fp32
    k_mma2<<<dim3(8, 24, 1), 512, SMEM_BYTES>>>(
        paoh, paol, pwoh, pwol, ppr, nullptr, nullptr,
        NB*TMM, DD, DD,
        DD, DD, 0, DD,
        0,0, 0,0, 0,0, 1, 1.0f, 0, 0);

    k_unmerge<<<dim3(TT, NB), 256>>>(out);
}

// round 12
// speedup vs baseline: 1.0355x; 1.0355x over previous
#include <cuda_runtime.h>
#include <cuda_bf16.h>
#include <math.h>
#include <stdint.h>

// Problem constants
#define NB   8
#define TT   512
#define DD   1024
#define TA   256
#define TB2  256
#define RM   128
#define TMM  384
#define NH   16
#define HD   64
#define NBINS 16384
#define CAP   4096
#define TARGETN 2048
#define SS   (TMM*TMM)

// ---------------- static device scratch ----------------
__device__ float              g_inorm[NB*TT];
__device__ float              g_psim[2*NB*65536];
__device__ unsigned int       g_keys[NB*65536];
__device__ unsigned int       g_hist[NB*NBINS];
__device__ int                g_thr[NB];
__device__ int                g_cnt[NB];
__device__ unsigned long long g_gath[NB*CAP];
__device__ int                g_amap[NB*TA];
__device__ int                g_bmap[NB*TB2];
__device__ int                g_kept[NB*RM];
// pre-split bf16 (hi/lo) operand buffers
__device__ unsigned short g_mh [NB*TMM*DD],   g_ml [NB*TMM*DD];
__device__ unsigned short g_wch[3*DD*DD],     g_wcl[3*DD*DD];
__device__ unsigned short g_woh[DD*DD],       g_wol[DD*DD];
__device__ unsigned short g_qkh[NB*TMM*3*DD], g_qkl[NB*TMM*3*DD];
__device__ float          g_s  [NB*NH*SS];
__device__ unsigned short g_ph [NB*NH*SS],    g_pl [NB*NH*SS];
__device__ unsigned short g_aoh[NB*TMM*DD],   g_aol[NB*TMM*DD];

// ---------------- helpers ----------------
__device__ __forceinline__ unsigned pk2u(unsigned short a, unsigned short b) {
    return (unsigned)a | ((unsigned)b << 16);
}
__device__ __forceinline__ void split2u(float v, unsigned short& h, unsigned short& l) {
    __nv_bfloat16 hb = __float2bfloat16_rn(v);
    __nv_bfloat16 lb = __float2bfloat16_rn(v - __bfloat162float(hb));
    h = __bfloat16_as_ushort(hb);
    l = __bfloat16_as_ushort(lb);
}

// ---------------- init ----------------
__global__ void k_init() {
    int i = blockIdx.x * blockDim.x + threadIdx.x;
    if (i < NB*NBINS) g_hist[i] = 0u;
    if (i < NB)       g_cnt[i]  = 0;
}

// ---------------- row inverse norms ----------------
__global__ void k_norm(const float* __restrict__ x) {
    int row  = blockIdx.x * 8 + (threadIdx.x >> 5);
    if (row >= NB*TT) return;
    int lane = threadIdx.x & 31;
    const float* p = x + (size_t)row * DD;
    float ss = 0.f;
    for (int i = lane; i < DD; i += 32) { float v = p[i]; ss += v*v; }
    #pragma unroll
    for (int o = 16; o; o >>= 1) ss += __shfl_xor_sync(0xffffffffu, ss, o);
    if (lane == 0) g_inorm[row] = 1.0f / fmaxf(sqrtf(ss), 1e-12f);
}

// ---------------- weight convert/split ----------------
__global__ void k_cvtW(const float* __restrict__ Wq, const float* __restrict__ Wk,
                       const float* __restrict__ Wv, const float* __restrict__ Wo) {
    int t = blockIdx.x * blockDim.x + threadIdx.x;
    int which = t >> 18, rem = t & 262143;
    const float* src = (which == 0) ? Wq : (which == 1) ? Wk : (which == 2) ? Wv : Wo;
    float4 v = *(const float4*)(src + (size_t)rem * 4);
    unsigned short h0,h1,h2,h3,l0,l1,l2,l3;
    split2u(v.x,h0,l0); split2u(v.y,h1,l1); split2u(v.z,h2,l2); split2u(v.w,h3,l3);
    uint2 hh = make_uint2(pk2u(h0,h1), pk2u(h2,h3));
    uint2 ll = make_uint2(pk2u(l0,l1), pk2u(l2,l3));
    if (which < 3) {
        *(uint2*)(g_wch + (size_t)t*4) = hh;
        *(uint2*)(g_wcl + (size_t)t*4) = ll;
    } else {
        *(uint2*)(g_woh + (size_t)rem*4) = hh;
        *(uint2*)(g_wol + (size_t)rem*4) = ll;
    }
}

// ---------------- cosine partial dots (K split in 2 halves, 512 blocks) ----------------
__global__ void k_sim(const float* __restrict__ x) {
    int z = blockIdx.z;
    int b = z & 7, half = z >> 3;
    int a0 = blockIdx.y * 64;
    int b0 = blockIdx.x * 32;
    int tid = threadIdx.x;
    int tx = tid & 15, ty = tid >> 4;
    __shared__ float As[16][68], Bs[16][36];
    const float* xb = x + (size_t)b * TT * DD;
    float acc[4][2];
    #pragma unroll
    for (int i = 0; i < 4; i++) { acc[i][0] = 0.f; acc[i][1] = 0.f; }

    int ar = tid >> 2, aq = tid & 3;
    int kbase = half * 512;
    for (int k0 = kbase; k0 < kbase + 512; k0 += 16) {
        float4 va = *(const float4*)(xb + (size_t)(2*(a0+ar)) * DD + k0 + aq*4);
        As[aq*4+0][ar]=va.x; As[aq*4+1][ar]=va.y; As[aq*4+2][ar]=va.z; As[aq*4+3][ar]=va.w;
        if (tid < 128) {
            int br = tid >> 2, bq = tid & 3;
            float4 vb = *(const float4*)(xb + (size_t)(2*(b0+br)+1) * DD + k0 + bq*4);
            Bs[bq*4+0][br]=vb.x; Bs[bq*4+1][br]=vb.y; Bs[bq*4+2][br]=vb.z; Bs[bq*4+3][br]=vb.w;
        }
        __syncthreads();
        #pragma unroll
        for (int kk = 0; kk < 16; kk++) {
            float4 a4 = *(const float4*)&As[kk][ty*4];
            float2 b2 = *(const float2*)&Bs[kk][tx*2];
            acc[0][0] += a4.x*b2.x; acc[0][1] += a4.x*b2.y;
            acc[1][0] += a4.y*b2.x; acc[1][1] += a4.y*b2.y;
            acc[2][0] += a4.z*b2.x; acc[2][1] += a4.z*b2.y;
            acc[3][0] += a4.w*b2.x; acc[3][1] += a4.w*b2.y;
        }
        __syncthreads();
    }
    size_t base = (size_t)(half*NB + b) * 65536;
    #pragma unroll
    for (int i = 0; i < 4; i++)
        #pragma unroll
        for (int j = 0; j < 2; j++) {
            int idx = (a0+ty*4+i) * TB2 + (b0+tx*2+j);
            g_psim[base + idx] = acc[i][j];
        }
}

// ---------------- combine halves, apply norms, keys + histogram ----------------
__global__ void k_simfin() {
    int i = blockIdx.x * blockDim.x + threadIdx.x;   // NB*65536 threads
    int b = i >> 16, idx = i & 65535;
    int a = idx >> 8, bb = idx & 255;
    float dot = g_psim[(size_t)b*65536 + i - (size_t)b*65536 + (size_t)b*65536] ; // placeholder avoided below
    dot = g_psim[(size_t)b*65536 + idx] + g_psim[(size_t)(NB + b)*65536 + idx];
    float sim = dot * g_inorm[b*TT + 2*a] * g_inorm[b*TT + 2*bb + 1];
    unsigned u = __float_as_uint(sim);
    u = (u & 0x80000000u) ? ~u : (u | 0x80000000u);
    g_keys[i] = u;
    atomicAdd(&g_hist[b*NBINS + (u >> 18)], 1u);
}

// ---------------- per-batch threshold bin (MLP-unrolled) ----------------
__global__ void k_thresh() {
    int b = blockIdx.x, t = threadIdx.x;
    __shared__ unsigned int csum[256];
    __shared__ unsigned int binbuf[64];
    __shared__ int sel;
    __shared__ unsigned int accbase;
    unsigned int a8[8] = {0,0,0,0,0,0,0,0};
    #pragma unroll
    for (int j = 0; j < 64; j++)
        a8[j & 7] += g_hist[b*NBINS + (NBINS-1 - (t*64 + j))];
    csum[t] = a8[0]+a8[1]+a8[2]+a8[3]+a8[4]+a8[5]+a8[6]+a8[7];
    __syncthreads();
    if (t == 0) {
        unsigned int acc = 0; int c = 0;
        for (; c < 256; c++) { if (acc + csum[c] >= TARGETN) break; acc += csum[c]; }
        sel = c; accbase = acc;
    }
    __syncthreads();
    int c = sel;
    if (c < 256 && t < 64) binbuf[t] = g_hist[b*NBINS + (NBINS-1 - c*64) - t];
    __syncthreads();
    if (t == 0) {
        int thr = 0;
        if (c < 256) {
            unsigned int acc = accbase;
            for (int j = 0; j < 64; j++) {
                acc += binbuf[j];
                if (acc >= TARGETN) { thr = NBINS-1 - c*64 - j; break; }
            }
        }
        g_thr[b] = thr;
    }
}

// ---------------- gather top entries ----------------
__global__ void k_gather() {
    int i = blockIdx.x * blockDim.x + threadIdx.x;
    int b = i >> 16, idx = i & 65535;
    unsigned int key = g_keys[i];
    if ((int)(key >> 18) >= g_thr[b]) {
        int pos = atomicAdd(&g_cnt[b], 1);
        if (pos < CAP)
            g_gath[b*CAP + pos] =
                ((unsigned long long)key << 16) | (unsigned long long)(65535 - idx);
    }
}

// ---------------- bitonic sort + serial greedy + maps ----------------
__global__ void k_sortgreedy() {
    int b = blockIdx.x, tid = threadIdx.x;
    __shared__ unsigned long long S[CAP];
    __shared__ unsigned long long red[1024];
    __shared__ unsigned char ua[TA], ub[TB2];
    __shared__ int pa[RM], pb[RM];
    __shared__ int sm_cnt;

    int cnt = g_cnt[b];
    int lim = (cnt <= CAP) ? cnt : 0;
    for (int i = tid; i < CAP; i += 1024) S[i] = (i < lim) ? g_gath[b*CAP + i] : 0ULL;
    for (int i = tid; i < TA;  i += 1024) { ua[i] = 0; ub[i] = 0; }
    if (tid == 0) sm_cnt = 0;
    __syncthreads();

    for (int size = 2; size <= CAP; size <<= 1)
        for (int stride = size >> 1; stride > 0; stride >>= 1) {
            for (int t = tid; t < CAP/2; t += 1024) {
                int pos = 2*t - (t & (stride - 1));
                unsigned long long x0 = S[pos], x1 = S[pos + stride];
                bool up = ((pos & size) == 0);
                if (up ? (x0 < x1) : (x0 > x1)) { S[pos] = x1; S[pos + stride] = x0; }
            }
            __syncthreads();
        }

    if (tid == 0) {
        int m = 0;
        for (int i = 0; i < CAP && m < RM; i++) {
            unsigned long long e = S[i];
            if (!e) break;
            int idx = 65535 - (int)(e & 0xFFFFULL);
            int a = idx >> 8, bb = idx & 255;
            if (!ua[a] && !ub[bb]) { ua[a] = 1; ub[bb] = 1; pa[m] = a; pb[m] = bb; m++; }
        }
        sm_cnt = m;
    }
    __syncthreads();

    while (sm_cnt < RM) {
        unsigned long long best = 0ULL;
        for (int i = tid; i < 65536; i += 1024) {
            int a = i >> 8, bb = i & 255;
            if (ua[a] || ub[bb]) continue;
            unsigned long long comp =
                ((unsigned long long)g_keys[b*65536 + i] << 16) |
                (unsigned long long)(65535 - i);
            if (comp > best) best = comp;
        }
        red[tid] = best;
        __syncthreads();
        for (int o = 512; o; o >>= 1) {
            if (tid < o) { unsigned long long v = red[tid + o]; if (v > red[tid]) red[tid] = v; }
            __syncthreads();
        }
        if (tid == 0) {
            unsigned long long e = red[0];
            int idx = 65535 - (int)(e & 0xFFFFULL);
            int a = idx >> 8, bb = idx & 255;
            ua[a] = 1; ub[bb] = 1; pa[sm_cnt] = a; pb[sm_cnt] = bb; sm_cnt++;
        }
        __syncthreads();
    }

    if (tid == 0) {
        for (int a = 0; a < TA; a++) g_amap[b*TA + a] = -1;
        for (int i = 0; i < RM; i++) g_amap[b*TA + pa[i]] = pb[i];
        int k = 0;
        for (int bb = 0; bb < TB2; bb++)
            if (!ub[bb]) { g_kept[b*RM + k] = bb; g_bmap[b*TB2 + bb] = TA + k; k++; }
        for (int i = 0; i < RM; i++) g_bmap[b*TB2 + pb[i]] = pa[i];
    }
}

// ---------------- build merged tokens (writes bf16 hi/lo) ----------------
__global__ void k_merge(const float* __restrict__ x) {
    int b = blockIdx.y, row = blockIdx.x, tid = threadIdx.x;
    const float* xb = x + (size_t)b * TT * DD;
    float4 v;
    if (row < TA) {
        const float4* ra = (const float4*)(xb + (size_t)(2*row) * DD);
        int mb = g_amap[b*TA + row];
        if (mb >= 0) {
            const float4* rb = (const float4*)(xb + (size_t)(2*mb + 1) * DD);
            float4 va = ra[tid], vb = rb[tid];
            v = make_float4(0.5f*(va.x+vb.x), 0.5f*(va.y+vb.y),
                            0.5f*(va.z+vb.z), 0.5f*(va.w+vb.w));
        } else v = ra[tid];
    } else {
        int bb = g_kept[b*RM + row - TA];
        v = ((const float4*)(xb + (size_t)(2*bb + 1) * DD))[tid];
    }
    unsigned short h0,h1,h2,h3,l0,l1,l2,l3;
    split2u(v.x,h0,l0); split2u(v.y,h1,l1); split2u(v.z,h2,l2); split2u(v.w,h3,l3);
    size_t e = ((size_t)b*TMM + row) * DD + tid*4;
    *(uint2*)(g_mh + e) = make_uint2(pk2u(h0,h1), pk2u(h2,h3));
    *(uint2*)(g_ml + e) = make_uint2(pk2u(l0,l1), pk2u(l2,l3));
}

// =======================================================================
//  Pre-split bf16x3 tensor-core GEMM, cp.async double-buffered, ldmatrix.
// =======================================================================
#define BK 32
#define SROW 40
#define ARR_ELEMS (128*SROW)
#define STAGE_ELEMS (4*ARR_ELEMS)
#define SMEM_BYTES (2*STAGE_ELEMS*2)

#define MMA_BF16(d, a, b) \
    asm volatile("mma.sync.aligned.m16n8k16.row.col.f32.bf16.bf16.f32 " \
                 "{%0,%1,%2,%3},{%4,%5,%6,%7},{%8,%9},{%0,%1,%2,%3};" \
                 : "+f"(d[0]), "+f"(d[1]), "+f"(d[2]), "+f"(d[3]) \
                 : "r"(a[0]), "r"(a[1]), "r"(a[2]), "r"(a[3]), "r"(b[0]), "r"(b[1]))

__device__ __forceinline__ void cp16(unsigned short* dst, const unsigned short* src) {
    unsigned s = (unsigned)__cvta_generic_to_shared(dst);
    asm volatile("cp.async.cg.shared.global [%0], [%1], 16;\n" :: "r"(s), "l"(src));
}

__device__ __forceinline__ void ldsmA(unsigned r[4], const unsigned short* base,
                                      int row0, int col0, int lane) {
    const unsigned short* p = base + (size_t)(row0 + ((lane>>3)&1)*8 + (lane&7))*SROW
                                   + col0 + ((lane>>4)&1)*8;
    unsigned a = (unsigned)__cvta_generic_to_shared(p);
    asm volatile("ldmatrix.sync.aligned.m8n8.x4.shared.b16 {%0,%1,%2,%3},[%4];"
                 : "=r"(r[0]), "=r"(r[1]), "=r"(r[2]), "=r"(r[3]) : "r"(a));
}
__device__ __forceinline__ void ldsmB(unsigned r[4], const unsigned short* base,
                                      int row0, int col0, int lane) {
    const unsigned short* p = base + (size_t)(row0 + ((lane>>4)&1)*8 + (lane&7))*SROW
                                   + col0 + ((lane>>3)&1)*8;
    unsigned a = (unsigned)__cvta_generic_to_shared(p);
    asm volatile("ldmatrix.sync.aligned.m8n8.x4.shared.b16 {%0,%1,%2,%3},[%4];"
                 : "=r"(r[0]), "=r"(r[1]), "=r"(r[2]), "=r"(r[3]) : "r"(a));
}

// unm=1: scatter fp32 rows through amap/kept to the final (B,512,1024) output
__device__ __forceinline__ void unm_store(float* Cf, int gm, int gn, float a, float b) {
    int bb = gm / TMM, r = gm - bb*TMM;
    int d0, d1 = -1;
    if (r < TA) {
        d0 = 2*r;
        int mb = g_amap[bb*TA + r];
        if (mb >= 0) d1 = 2*mb + 1;
    } else {
        d0 = 2*g_kept[bb*RM + (r - TA)] + 1;
    }
    float2 v = make_float2(a, b);
    *(float2*)(Cf + ((size_t)bb*TT + d0)*DD + gn) = v;
    if (d1 >= 0) *(float2*)(Cf + ((size_t)bb*TT + d1)*DD + gn) = v;
}

__global__ __launch_bounds__(512)
void k_mma2(const unsigned short* __restrict__ Ahg, const unsigned short* __restrict__ Alg,
            const unsigned short* __restrict__ Bhg, const unsigned short* __restrict__ Blg,
            float* __restrict__ Cf, unsigned short* __restrict__ Ch, unsigned short* __restrict__ Cl,
            int M, int N, int K,
            long sAm, long sBn, long sBk, long sCm,
            long bAo, long bAi, long bBo, long bBi, long bCo, long bCi,
            int inner, float alpha, int modeB, int nlay, int unm)
{
    extern __shared__ unsigned short sm_[];
    int z = blockIdx.z, zo = z / inner, zi = z % inner;
    Ahg += (size_t)zo*bAo + (size_t)zi*bAi;
    Alg += (size_t)zo*bAo + (size_t)zi*bAi;
    Bhg += (size_t)zo*bBo + (size_t)zi*bBi;
    Blg += (size_t)zo*bBo + (size_t)zi*bBi;
    size_t coff = (size_t)zo*bCo + (size_t)zi*bCi;
    int m0 = blockIdx.y * 128, n0 = blockIdx.x * 128;

    int tid  = threadIdx.x;
    int warp = tid >> 5, lane = tid & 31;
    int g    = lane >> 2, tg = lane & 3;
    int wm, wn, MT;
    if (!nlay) { wm = (warp >> 2) * 32; wn = (warp & 3) * 32; MT = 2; }
    else       { wm = (warp & 7) * 16;  wn = (warp >> 3) * 32; MT = 1; }

    float acc[2][4][4];
    #pragma unroll
    for (int i = 0; i < 2; i++)
        #pragma unroll
        for (int j = 0; j < 4; j++)
            #pragma unroll
            for (int c = 0; c < 4; c++) acc[i][j][c] = 0.f;

    const int ntiles = K / BK;

    auto fill = [&](int stage, int k0) {
        unsigned short* sb = sm_ + stage * STAGE_ELEMS;
        if (!modeB) {
            #pragma unroll
            for (int i = 0; i < 4; i++) {
                int c = tid + i*512;
                int arr = c >> 9, rem = c & 511;
                int row = rem >> 2, q = rem & 3;
                const unsigned short* src;
                if      (arr == 0) src = Ahg + (size_t)(m0+row)*sAm + k0 + q*8;
                else if (arr == 1) src = Alg + (size_t)(m0+row)*sAm + k0 + q*8;
                else if (arr == 2) src = Bhg + (size_t)(n0+row)*sBn + k0 + q*8;
                else               src = Blg + (size_t)(n0+row)*sBn + k0 + q*8;
                cp16(sb + arr*ARR_ELEMS + row*SROW + q*8, src);
            }
        } else {
            #pragma unroll
            for (int i = 0; i < 2; i++) {
                int c = tid + i*512;
                int arr = c >> 9, rem = c & 511;
                int row = rem >> 2, q = rem & 3;
                const unsigned short* src = (arr ? Alg : Ahg) + (size_t)(m0+row)*sAm + k0 + q*8;
                cp16(sb + arr*ARR_ELEMS + row*SROW + q*8, src);
            }
            #pragma unroll
            for (int i = 0; i < 8; i++) {
                int s = tid + i*512;
                int n = s & 127, kk = s >> 7;
                int gn = n0 + n;
                if (gn < N) {
                    size_t off = (size_t)gn + (size_t)(k0 + kk) * sBk;
                    sb[2*ARR_ELEMS + n*SROW + kk] = Bhg[off];
                    sb[3*ARR_ELEMS + n*SROW + kk] = Blg[off];
                }
            }
        }
    };

    fill(0, 0);
    asm volatile("cp.async.commit_group;\n");

    for (int t = 0; t < ntiles; t++) {
        if (t + 1 < ntiles) fill((t+1) & 1, (t+1)*BK);
        asm volatile("cp.async.commit_group;\n");
        asm volatile("cp.async.wait_group 1;\n");
        __syncthreads();

        const unsigned short* sb = sm_ + (t & 1) * STAGE_ELEMS;
        const unsigned short* Ahs = sb;
        const unsigned short* Als = sb + ARR_ELEMS;
        const unsigned short* Bhs = sb + 2*ARR_ELEMS;
        const unsigned short* Bls = sb + 3*ARR_ELEMS;

        #pragma unroll
        for (int kc = 0; kc < 2; kc++) {
            int kb = kc*16;
            unsigned ah[2][4], al[2][4], bh[4][2], bl[4][2];
            #pragma unroll
            for (int mt = 0; mt < 2; mt++) {
                if (mt < MT) {
                    ldsmA(ah[mt], Ahs, wm + mt*16, kb, lane);
                    ldsmA(al[mt], Als, wm + mt*16, kb, lane);
                }
            }
            {
                unsigned tmp[4];
                ldsmB(tmp, Bhs, wn, kb, lane);
                bh[0][0]=tmp[0]; bh[0][1]=tmp[1]; bh[1][0]=tmp[2]; bh[1][1]=tmp[3];
                ldsmB(tmp, Bhs, wn + 16, kb, lane);
                bh[2][0]=tmp[0]; bh[2][1]=tmp[1]; bh[3][0]=tmp[2]; bh[3][1]=tmp[3];
                ldsmB(tmp, Bls, wn, kb, lane);
                bl[0][0]=tmp[0]; bl[0][1]=tmp[1]; bl[1][0]=tmp[2]; bl[1][1]=tmp[3];
                ldsmB(tmp, Bls, wn + 16, kb, lane);
                bl[2][0]=tmp[0]; bl[2][1]=tmp[1]; bl[3][0]=tmp[2]; bl[3][1]=tmp[3];
            }
            #pragma unroll
            for (int mt = 0; mt < 2; mt++) if (mt < MT)
                #pragma unroll
                for (int nt = 0; nt < 4; nt++) MMA_BF16(acc[mt][nt], ah[mt], bh[nt]);
            #pragma unroll
            for (int mt = 0; mt < 2; mt++) if (mt < MT)
                #pragma unroll
                for (int nt = 0; nt < 4; nt++) MMA_BF16(acc[mt][nt], ah[mt], bl[nt]);
            #pragma unroll
            for (int mt = 0; mt < 2; mt++) if (mt < MT)
                #pragma unroll
                for (int nt = 0; nt < 4; nt++) MMA_BF16(acc[mt][nt], al[mt], bh[nt]);
        }
        __syncthreads();
    }

    // ---- epilogue ----
    #pragma unroll
    for (int mt = 0; mt < 2; mt++) {
        if (mt >= MT) continue;
        #pragma unroll
        for (int nt = 0; nt < 4; nt++) {
            int gm = m0 + wm + mt*16 + g;
            int gn = n0 + wn + nt*8 + 2*tg;
            if (gn >= N) continue;
            float v0 = alpha*acc[mt][nt][0], v1 = alpha*acc[mt][nt][1];
            float v2 = alpha*acc[mt][nt][2], v3 = alpha*acc[mt][nt][3];
            if (Cf) {
                if (unm) {
                    unm_store(Cf, gm,     gn, v0, v1);
                    unm_store(Cf, gm + 8, gn, v2, v3);
                } else {
                    if (gm < M)     *(float2*)(Cf + coff + (size_t)gm*sCm + gn)     = make_float2(v0, v1);
                    if (gm + 8 < M) *(float2*)(Cf + coff + (size_t)(gm+8)*sCm + gn) = make_float2(v2, v3);
                }
            }
            if (Ch) {
                unsigned short h0,h1,h2,h3,l0,l1,l2,l3;
                split2u(v0,h0,l0); split2u(v1,h1,l1); split2u(v2,h2,l2); split2u(v3,h3,l3);
                if (gm < M) {
                    *(unsigned*)(Ch + coff + (size_t)gm*sCm + gn) = pk2u(h0,h1);
                    *(unsigned*)(Cl + coff + (size_t)gm*sCm + gn) = pk2u(l0,l1);
                }
                if (gm + 8 < M) {
                    *(unsigned*)(Ch + coff + (size_t)(gm+8)*sCm + gn) = pk2u(h2,h3);
                    *(unsigned*)(Cl + coff + (size_t)(gm+8)*sCm + gn) = pk2u(l2,l3);
                }
            }
        }
    }
}

// ---------------- softmax over rows of 384 ----------------
__global__ void k_softmax() {
    int row = blockIdx.x, tid = threadIdx.x;
    float* p = g_s + (size_t)row * TMM;
    float v0 = p[tid], v1 = p[tid + 128], v2 = p[tid + 256];
    float mx = fmaxf(v0, fmaxf(v1, v2));
    __shared__ float sw[4], sw2[4];
    #pragma unroll
    for (int o = 16; o; o >>= 1) mx = fmaxf(mx, __shfl_xor_sync(0xffffffffu, mx, o));
    if ((tid & 31) == 0) sw[tid >> 5] = mx;
    __syncthreads();
    mx = fmaxf(fmaxf(sw[0], sw[1]), fmaxf(sw[2], sw[3]));
    v0 = expf(v0 - mx); v1 = expf(v1 - mx); v2 = expf(v2 - mx);
    float s = v0 + v1 + v2;
    #pragma unroll
    for (int o = 16; o; o >>= 1) s += __shfl_xor_sync(0xffffffffu, s, o);
    if ((tid & 31) == 0) sw2[tid >> 5] = s;
    __syncthreads();
    s = sw2[0] + sw2[1] + sw2[2] + sw2[3];
    float inv = 1.0f / s;
    size_t base = (size_t)row * TMM;
    unsigned short h, l;
    split2u(v0*inv, h, l); g_ph[base + tid]       = h; g_pl[base + tid]       = l;
    split2u(v1*inv, h, l); g_ph[base + tid + 128] = h; g_pl[base + tid + 128] = l;
    split2u(v2*inv, h, l); g_ph[base + tid + 256] = h; g_pl[base + tid + 256] = l;
}

// ---------------- launch ----------------
extern "C" void kernel_launch(void* const* d_in, const int* in_sizes, int n_in,
                              void* d_out, int out_size) {
    (void)in_sizes; (void)n_in; (void)out_size;
    const float* x  = (const float*)d_in[0];
    const float* Wq = (const float*)d_in[1];
    const float* Wk = (const float*)d_in[2];
    const float* Wv = (const float*)d_in[3];
    const float* Wo = (const float*)d_in[4];
    float* out = (float*)d_out;

    static cudaStream_t s1 = nullptr;
    static cudaEvent_t evRoot = nullptr, evMatch = nullptr;
    if (!s1) {
        cudaFuncSetAttribute(k_mma2, cudaFuncAttributeMaxDynamicSharedMemorySize, SMEM_BYTES);
        cudaStreamCreateWithFlags(&s1, cudaStreamNonBlocking);
        cudaEventCreateWithFlags(&evRoot,  cudaEventDisableTiming);
        cudaEventCreateWithFlags(&evMatch, cudaEventDisableTiming);
    }

    unsigned short *pmh,*pml,*pwch,*pwcl,*pwoh,*pwol,*pqkh,*pqkl,*pph,*ppl,*paoh,*paol;
    float *ps;
    cudaGetSymbolAddress((void**)&pmh,  g_mh);  cudaGetSymbolAddress((void**)&pml,  g_ml);
    cudaGetSymbolAddress((void**)&pwch, g_wch); cudaGetSymbolAddress((void**)&pwcl, g_wcl);
    cudaGetSymbolAddress((void**)&pwoh, g_woh); cudaGetSymbolAddress((void**)&pwol, g_wol);
    cudaGetSymbolAddress((void**)&pqkh, g_qkh); cudaGetSymbolAddress((void**)&pqkl, g_qkl);
    cudaGetSymbolAddress((void**)&pph,  g_ph);  cudaGetSymbolAddress((void**)&ppl,  g_pl);
    cudaGetSymbolAddress((void**)&paoh, g_aoh); cudaGetSymbolAddress((void**)&paol, g_aol);
    cudaGetSymbolAddress((void**)&ps,   g_s);

    // ---- fork: match pipeline on s1; cvtW overlaps on main ----
    cudaEventRecord(evRoot, 0);
    cudaStreamWaitEvent(s1, evRoot, 0);
    k_init<<<(NB*NBINS + 255)/256, 256, 0, s1>>>();
    k_norm<<<NB*TT/8, 256, 0, s1>>>(x);
    k_sim<<<dim3(8, 4, NB*2), 256, 0, s1>>>(x);
    k_simfin<<<NB*65536/256, 256, 0, s1>>>();
    k_thresh<<<NB, 256, 0, s1>>>();
    k_gather<<<512, 1024, 0, s1>>>();
    k_sortgreedy<<<NB, 1024, 0, s1>>>();
    cudaEventRecord(evMatch, s1);

    k_cvtW<<<4096, 256>>>(Wq, Wk, Wv, Wo);

    cudaStreamWaitEvent(0, evMatch, 0);
    k_merge<<<dim3(TMM, NB), 256>>>(x);

    const long MD3 = (long)TMM * 3 * DD;

    // fused QKV projection: (3072 x 3072) = merged(3072x1024) @ Wcat^T -> split bf16
    k_mma2<<<dim3(24, 24, 1), 512, SMEM_BYTES>>>(
        pmh, pml, pwch, pwcl, nullptr, pqkh, pqkl,
        NB*TMM, 3*DD, DD,
        DD, DD, 0, 3*DD,
        0,0, 0,0, 0,0, 1, 1.0f, 0, 0, 0);

    // scores: per (b,h): (384x384) = Q_bh @ K_bh^T / 8  -> fp32
    k_mma2<<<dim3(3, 3, NB*NH), 512, SMEM_BYTES>>>(
        pqkh, pqkl, pqkh + DD, pqkl + DD, ps, nullptr, nullptr,
        TMM, TMM, HD,
        3*DD, 3*DD, 0, TMM,
        MD3, (long)HD, MD3, (long)HD, (long)NH*SS, (long)SS, NH, 0.125f, 0, 0, 0);

    k_softmax<<<NB*NH*TMM, 128>>>();

    // attn @ V: per (b,h): (384x64) = P @ V_bh  (nlay=1: 8x2 warp layout)
    k_mma2<<<dim3(1, 3, NB*NH), 512, SMEM_BYTES>>>(
        pph, ppl, pqkh + 2*DD, pqkl + 2*DD, nullptr, paoh, paol,
        TMM, HD, TMM,
        TMM, 0, 3*DD, DD,
        (long)NH*SS, (long)SS, MD3, (long)HD, (long)TMM*DD, (long)HD, NH, 1.0f, 1, 1, 0);

    // output projection -> fp32, fused unmerge scatter straight into out
    k_mma2<<<dim3(8, 24, 1), 512, SMEM_BYTES>>>(
        paoh, paol, pwoh, pwol, out, nullptr, nullptr,
        NB*TMM, DD, DD,
        DD, DD, 0, DD,
        0,0, 0,0, 0,0, 1, 1.0f, 0, 0, 1);
}